// round 1
// baseline (speedup 1.0000x reference)
#include <cuda_runtime.h>
#include <math.h>

// Problem constants
#define Bq 8
#define Sq 1024
#define Dq 1024
#define Fq 3584
#define Eq 2
#define EPSq 1e-6f

#define ISPLIT 16   // i-chunks for gate/up
#define FSPLIT 14   // f-chunks for down

// ---------------- scratch (device globals; no allocation) ----------------
__device__ float g_h1[Bq * Dq];      // rmsnorm(x0)*ln1_w
__device__ float g_v0[Bq * Dq];      // h1 @ v_w
__device__ float g_attn[Bq * Dq];    // v0 @ o_w
__device__ float g_xmid[Bq * Dq];    // x0 + attn
__device__ float g_h2[Bq * Dq];      // rmsnorm(xmid)*ln2_w
__device__ float g_topw[Bq];
__device__ int   g_sel[Bq];
__device__ int   g_used[Eq];

__device__ float g_pg[(size_t)Eq * ISPLIT * Bq * Fq];  // gate partials
__device__ float g_pu[(size_t)Eq * ISPLIT * Bq * Fq];  // up partials
__device__ float g_t [(size_t)Eq * Bq * Fq];           // masked scaled activation
__device__ float g_py[(size_t)Eq * FSPLIT * Bq * Dq];  // down partials

// ---------------- helpers ----------------
__device__ __forceinline__ float block_sum(float v, float* sb) {
    int lane = threadIdx.x & 31;
    int w    = threadIdx.x >> 5;
    int nw   = blockDim.x >> 5;
#pragma unroll
    for (int o = 16; o; o >>= 1) v += __shfl_xor_sync(0xffffffffu, v, o);
    __syncthreads();            // protect sb reuse across calls
    if (lane == 0) sb[w] = v;
    __syncthreads();
    if (w == 0) {
        float r = (lane < nw) ? sb[lane] : 0.f;
#pragma unroll
        for (int o = 16; o; o >>= 1) r += __shfl_xor_sync(0xffffffffu, r, o);
        if (lane == 0) sb[0] = r;
    }
    __syncthreads();
    return sb[0];
}

// ---------------- K1: h1 = rmsnorm(x0)*ln1_w; zero accumulators ----------------
__global__ void k_prep(const float* __restrict__ hidden, const float* __restrict__ ln1w) {
    __shared__ float sb[32];
    int b = blockIdx.x, t = threadIdx.x;
    const float* x = hidden + (size_t)b * Sq * Dq;  // token 0
    float ss = 0.f;
    for (int d = t; d < Dq; d += blockDim.x) { float v = x[d]; ss += v * v; }
    ss = block_sum(ss, sb);
    float rs = rsqrtf(ss / (float)Dq + EPSq);
    for (int d = t; d < Dq; d += blockDim.x) {
        g_h1[b * Dq + d]   = x[d] * rs * ln1w[d];
        g_v0[b * Dq + d]   = 0.f;
        g_attn[b * Dq + d] = 0.f;
    }
    if (b == 0 && t < Eq) g_used[t] = 0;
}

// ---------------- K2/K3: 8-batch matvec, out += in @ W (DxD) ----------------
// MODE 0: g_v0 += g_h1 @ W ; MODE 1: g_attn += g_v0 @ W
template <int MODE>
__global__ void __launch_bounds__(256) k_mv(const float* __restrict__ W) {
    const float* in  = MODE ? g_v0 : g_h1;
    float*       out = MODE ? g_attn : g_v0;
    int j0 = threadIdx.x * 4;                 // 256 threads * 4 = 1024 outputs
    int i0 = blockIdx.x * (Dq / 8);           // 8 i-chunks of 128
    float4 acc[Bq];
#pragma unroll
    for (int b = 0; b < Bq; b++) acc[b] = make_float4(0.f, 0.f, 0.f, 0.f);
#pragma unroll 4
    for (int i = i0; i < i0 + Dq / 8; i++) {
        float4 w = __ldg((const float4*)(W + (size_t)i * Dq + j0));
#pragma unroll
        for (int b = 0; b < Bq; b++) {
            float h = __ldg(&in[b * Dq + i]);
            acc[b].x += h * w.x; acc[b].y += h * w.y;
            acc[b].z += h * w.z; acc[b].w += h * w.w;
        }
    }
#pragma unroll
    for (int b = 0; b < Bq; b++) {
        atomicAdd(&out[b * Dq + j0 + 0], acc[b].x);
        atomicAdd(&out[b * Dq + j0 + 1], acc[b].y);
        atomicAdd(&out[b * Dq + j0 + 2], acc[b].z);
        atomicAdd(&out[b * Dq + j0 + 3], acc[b].w);
    }
}

// ---------------- K4: residual + rmsnorm + router / top-1 ----------------
__global__ void k_mid(const float* __restrict__ hidden, const float* __restrict__ ln2w,
                      const float* __restrict__ rw) {
    __shared__ float sb[32];
    int b = blockIdx.x, t = threadIdx.x;
    const float* x = hidden + (size_t)b * Sq * Dq;
    float ss = 0.f;
    for (int d = t; d < Dq; d += blockDim.x) {
        float v = x[d] + g_attn[b * Dq + d];
        g_xmid[b * Dq + d] = v;
        ss += v * v;
    }
    ss = block_sum(ss, sb);
    float rs = rsqrtf(ss / (float)Dq + EPSq);
    float l0 = 0.f, l1 = 0.f;
    for (int d = t; d < Dq; d += blockDim.x) {
        float h = g_xmid[b * Dq + d] * rs * ln2w[d];
        g_h2[b * Dq + d] = h;
        l0 += h * rw[d * 2 + 0];
        l1 += h * rw[d * 2 + 1];
    }
    l0 = block_sum(l0, sb);
    l1 = block_sum(l1, sb);
    if (t == 0) {
        int sel = (l1 > l0) ? 1 : 0;                    // argmax, ties -> 0
        float topw = 1.f / (1.f + expf(-fabsf(l0 - l1)));  // max softmax prob
        g_sel[b] = sel;
        g_topw[b] = topw;
        g_used[sel] = 1;
    }
}

// ---------------- K5: gate/up partial matvecs (weight streaming) ----------------
__global__ void __launch_bounds__(128) k_gateup(const float* __restrict__ gw,
                                                const float* __restrict__ uw) {
    int e = blockIdx.z;
    if (!g_used[e]) return;
    int f0 = blockIdx.x * 512 + threadIdx.x * 4;   // 7 * 512 = 3584
    int i0 = blockIdx.y * (Dq / ISPLIT);           // 64 rows per chunk
    const float* gb = gw + (size_t)e * Dq * Fq;
    const float* ub = uw + (size_t)e * Dq * Fq;
    float4 ag[Bq], au[Bq];
#pragma unroll
    for (int b = 0; b < Bq; b++) {
        ag[b] = make_float4(0.f, 0.f, 0.f, 0.f);
        au[b] = make_float4(0.f, 0.f, 0.f, 0.f);
    }
#pragma unroll 2
    for (int i = i0; i < i0 + Dq / ISPLIT; i++) {
        float4 wg = __ldg((const float4*)(gb + (size_t)i * Fq + f0));
        float4 wu = __ldg((const float4*)(ub + (size_t)i * Fq + f0));
        float hb[Bq];
#pragma unroll
        for (int b = 0; b < Bq; b++) hb[b] = __ldg(&g_h2[b * Dq + i]);
#pragma unroll
        for (int b = 0; b < Bq; b++) {
            ag[b].x += hb[b] * wg.x; ag[b].y += hb[b] * wg.y;
            ag[b].z += hb[b] * wg.z; ag[b].w += hb[b] * wg.w;
            au[b].x += hb[b] * wu.x; au[b].y += hb[b] * wu.y;
            au[b].z += hb[b] * wu.z; au[b].w += hb[b] * wu.w;
        }
    }
    size_t base = ((size_t)(e * ISPLIT + blockIdx.y) * Bq) * Fq + f0;
#pragma unroll
    for (int b = 0; b < Bq; b++) {
        *(float4*)(g_pg + base + (size_t)b * Fq) = ag[b];
        *(float4*)(g_pu + base + (size_t)b * Fq) = au[b];
    }
}

// ---------------- K6: reduce partials, silu, mask+scale -> t ----------------
__global__ void k_act() {
    int e = blockIdx.y;
    if (!g_used[e]) return;   // K7 gated too; t not read for unused expert
    int f = blockIdx.x * blockDim.x + threadIdx.x;
#pragma unroll
    for (int b = 0; b < Bq; b++) {
        float tv = 0.f;
        if (g_sel[b] == e) {
            float gg = 0.f, uu = 0.f;
#pragma unroll
            for (int iy = 0; iy < ISPLIT; iy++) {
                size_t idx = ((size_t)(e * ISPLIT + iy) * Bq + b) * Fq + f;
                gg += g_pg[idx];
                uu += g_pu[idx];
            }
            float sig = 1.f / (1.f + expf(-gg));
            tv = g_topw[b] * gg * sig * uu;
        }
        g_t[((size_t)e * Bq + b) * Fq + f] = tv;
    }
}

// ---------------- K7: down-projection partials ----------------
__global__ void __launch_bounds__(256) k_down(const float* __restrict__ dw) {
    int e    = blockIdx.z;
    int d    = blockIdx.x * 256 + threadIdx.x;
    int f0   = blockIdx.y * (Fq / FSPLIT);  // 256
    int slot = e * FSPLIT + blockIdx.y;
    float acc[Bq];
#pragma unroll
    for (int b = 0; b < Bq; b++) acc[b] = 0.f;
    if (g_used[e]) {
        const float* wb = dw + (size_t)e * Fq * Dq;
        for (int f = f0; f < f0 + Fq / FSPLIT; f += 4) {
            float4 tq[Bq];
#pragma unroll
            for (int b = 0; b < Bq; b++)
                tq[b] = *(const float4*)(g_t + ((size_t)e * Bq + b) * Fq + f);
            float w0 = __ldg(wb + (size_t)(f + 0) * Dq + d);
            float w1 = __ldg(wb + (size_t)(f + 1) * Dq + d);
            float w2 = __ldg(wb + (size_t)(f + 2) * Dq + d);
            float w3 = __ldg(wb + (size_t)(f + 3) * Dq + d);
#pragma unroll
            for (int b = 0; b < Bq; b++)
                acc[b] += tq[b].x * w0 + tq[b].y * w1 + tq[b].z * w2 + tq[b].w * w3;
        }
    }
#pragma unroll
    for (int b = 0; b < Bq; b++)
        g_py[((size_t)slot * Bq + b) * Dq + d] = acc[b];
}

// ---------------- K8: residual + final rmsnorm + score head ----------------
__global__ void k_final(const float* __restrict__ flnw, const float* __restrict__ sw,
                        float* __restrict__ out) {
    __shared__ float xs[Dq];
    __shared__ float sb[32];
    int b = blockIdx.x, t = threadIdx.x;
    float ss = 0.f;
    for (int d = t; d < Dq; d += blockDim.x) {
        float v = g_xmid[b * Dq + d];
#pragma unroll
        for (int s = 0; s < Eq * FSPLIT; s++) v += g_py[((size_t)s * Bq + b) * Dq + d];
        xs[d] = v;
        ss += v * v;
    }
    ss = block_sum(ss, sb);
    float rs = rsqrtf(ss / (float)Dq + EPSq);
    float p0 = 0.f, p1 = 0.f;
    for (int d = t; d < Dq; d += blockDim.x) {
        float xn = xs[d] * rs * flnw[d];
        p0 += xn * sw[d * 2 + 0];
        p1 += xn * sw[d * 2 + 1];
    }
    p0 = block_sum(p0, sb);
    p1 = block_sum(p1, sb);
    if (t == 0) {
        out[b * 2 + 0] = p0;
        out[b * 2 + 1] = p1;
    }
}

// ---------------- launch ----------------
extern "C" void kernel_launch(void* const* d_in, const int* in_sizes, int n_in,
                              void* d_out, int out_size) {
    (void)in_sizes; (void)n_in; (void)out_size;
    const float* hidden = (const float*)d_in[0];
    const float* ln1w   = (const float*)d_in[1];
    // d_in[2] = q_w, d_in[3] = k_w : provably unused (causal token-0 softmax == 1)
    const float* vw     = (const float*)d_in[4];
    const float* ow     = (const float*)d_in[5];
    const float* ln2w   = (const float*)d_in[6];
    const float* rw     = (const float*)d_in[7];
    const float* gw     = (const float*)d_in[8];
    const float* uw     = (const float*)d_in[9];
    const float* dw     = (const float*)d_in[10];
    const float* flnw   = (const float*)d_in[11];
    const float* sw     = (const float*)d_in[12];
    float* out = (float*)d_out;

    k_prep<<<Bq, 256>>>(hidden, ln1w);
    k_mv<0><<<8, 256>>>(vw);
    k_mv<1><<<8, 256>>>(ow);
    k_mid<<<Bq, 256>>>(hidden, ln2w, rw);
    k_gateup<<<dim3(7, ISPLIT, Eq), 128>>>(gw, uw);
    k_act<<<dim3(Fq / 256, Eq), 256>>>();
    k_down<<<dim3(Dq / 256, FSPLIT, Eq), 256>>>(dw);
    k_final<<<Bq, 256>>>(flnw, sw, out);
}

// round 2
// speedup vs baseline: 4.2137x; 4.2137x over previous
#include <cuda_runtime.h>
#include <math.h>

#define Bq 8
#define Sq 1024
#define Dq 1024
#define Fq 3584
#define Eq 2
#define NB 296
#define NT 256
#define EPSq 1e-6f

// ---------------- device scratch (no allocation) ----------------
__device__ float g_pv[16 * Bq * Dq];        // v0 partials [ic][b][j]
__device__ float g_attn[Bq * Dq];           // attn output (atomic)
__device__ float g_accg[Eq * Bq * Fq];      // gate acc (atomic)
__device__ float g_accu[Eq * Bq * Fq];      // up acc (atomic)
__device__ float g_y[Bq * Dq];              // moe output (atomic)
__device__ unsigned g_barc = 0;             // barrier arrive count
__device__ unsigned g_barg = 0;             // barrier generation

// ---------------- software grid barrier ----------------
__device__ __forceinline__ void grid_bar() {
    __syncthreads();
    if (threadIdx.x == 0) {
        __threadfence();
        unsigned old = *(volatile unsigned*)&g_barg;
        if (atomicAdd(&g_barc, 1u) == (unsigned)gridDim.x - 1u) {
            g_barc = 0;
            __threadfence();
            atomicExch(&g_barg, old + 1u);
        } else {
            while (*(volatile unsigned*)&g_barg == old) __nanosleep(64);
        }
        __threadfence();
    }
    __syncthreads();
}

// ---------------- multi-value block reduction (256 thr = 8 warps) ----------
template <int NV>
__device__ __forceinline__ void breduce(const float* v, float* s_red, float* s_out) {
    int lane = threadIdx.x & 31, w = threadIdx.x >> 5;
#pragma unroll
    for (int k = 0; k < NV; k++) {
        float x = v[k];
#pragma unroll
        for (int o = 16; o; o >>= 1) x += __shfl_xor_sync(0xffffffffu, x, o);
        if (lane == 0) s_red[k * 8 + w] = x;
    }
    __syncthreads();
    if (threadIdx.x < NV) {
        float s = 0.f;
#pragma unroll
        for (int j = 0; j < 8; j++) s += s_red[threadIdx.x * 8 + j];
        s_out[threadIdx.x] = s;
    }
    __syncthreads();
}

__global__ void __launch_bounds__(NT, 2) fused_all(
    const float* __restrict__ hidden, const float* __restrict__ ln1w,
    const float* __restrict__ vw, const float* __restrict__ ow,
    const float* __restrict__ ln2w, const float* __restrict__ rw,
    const float* __restrict__ gw, const float* __restrict__ uw,
    const float* __restrict__ dw, const float* __restrict__ flnw,
    const float* __restrict__ sw, float* __restrict__ out)
{
    __shared__ float s_h[Bq * Dq];   // 32KB multi-purpose: h1 / v0-chunk / h2 / t
    __shared__ float s_red[16 * 8];
    __shared__ float s_out[16];
    __shared__ float s_rs[Bq];
    __shared__ int   s_sel[Bq];
    __shared__ float s_tw[Bq];

    const int tid = threadIdx.x;
    const int blk = blockIdx.x;

    // ============ Stage A ============
    // A0: zero atomic accumulators
    for (int idx = blk * NT + tid; idx < Eq * Bq * Fq; idx += NB * NT) {
        g_accg[idx] = 0.f; g_accu[idx] = 0.f;
    }
    for (int idx = blk * NT + tid; idx < Bq * Dq; idx += NB * NT) {
        g_attn[idx] = 0.f; g_y[idx] = 0.f;
    }

    // A1: redundant per-block h1 = rmsnorm(x0) * ln1_w  (into smem)
    {
        float ss[Bq];
#pragma unroll
        for (int b = 0; b < Bq; b++) ss[b] = 0.f;
#pragma unroll
        for (int it = 0; it < 4; it++) {
            int d = tid + it * 256;
#pragma unroll
            for (int b = 0; b < Bq; b++) {
                float v = hidden[(size_t)b * Sq * Dq + d];
                ss[b] += v * v;
            }
        }
        breduce<Bq>(ss, s_red, s_out);
        if (tid < Bq) s_rs[tid] = rsqrtf(s_out[tid] * (1.f / Dq) + EPSq);
        __syncthreads();
#pragma unroll
        for (int it = 0; it < 4; it++) {
            int d = tid + it * 256;
            float lw = ln1w[d];
#pragma unroll
            for (int b = 0; b < Bq; b++)
                s_h[b * Dq + d] = hidden[(size_t)b * Sq * Dq + d] * s_rs[b] * lw;
        }
        __syncthreads();
    }

    // A2: v0 partial matvec (64 tasks: 16 i-chunks x 4 j-chunks)
    if (blk < 64) {
        int ic = blk >> 2, jc = blk & 3;
        int j = jc * 256 + tid, ib = ic * 64;
        float acc[Bq];
#pragma unroll
        for (int b = 0; b < Bq; b++) acc[b] = 0.f;
        for (int i4 = 0; i4 < 64; i4 += 4) {
            int i = ib + i4;
            float w0 = vw[(size_t)(i + 0) * Dq + j];
            float w1 = vw[(size_t)(i + 1) * Dq + j];
            float w2 = vw[(size_t)(i + 2) * Dq + j];
            float w3 = vw[(size_t)(i + 3) * Dq + j];
#pragma unroll
            for (int b = 0; b < Bq; b++) {
                float4 h4 = *(const float4*)&s_h[b * Dq + i];
                acc[b] = fmaf(h4.x, w0, acc[b]);
                acc[b] = fmaf(h4.y, w1, acc[b]);
                acc[b] = fmaf(h4.z, w2, acc[b]);
                acc[b] = fmaf(h4.w, w3, acc[b]);
            }
        }
#pragma unroll
        for (int b = 0; b < Bq; b++)
            g_pv[((size_t)ic * Bq + b) * Dq + j] = acc[b];
    }
    grid_bar();

    // ============ Stage B: attn = v0 @ o_w ============
    if (blk < 64) {
        int ic = blk >> 2, jc = blk & 3;
        // gather v0 chunk [b][0..63] into s_h (reuse)
        for (int idx = tid; idx < Bq * 64; idx += NT) {
            int b = idx >> 6, il = idx & 63;
            float s = 0.f;
#pragma unroll
            for (int c = 0; c < 16; c++)
                s += g_pv[((size_t)c * Bq + b) * Dq + ic * 64 + il];
            s_h[idx] = s;
        }
        __syncthreads();
        int j = jc * 256 + tid, ib = ic * 64;
        float acc[Bq];
#pragma unroll
        for (int b = 0; b < Bq; b++) acc[b] = 0.f;
        for (int i4 = 0; i4 < 64; i4 += 4) {
            int i = ib + i4;
            float w0 = ow[(size_t)(i + 0) * Dq + j];
            float w1 = ow[(size_t)(i + 1) * Dq + j];
            float w2 = ow[(size_t)(i + 2) * Dq + j];
            float w3 = ow[(size_t)(i + 3) * Dq + j];
#pragma unroll
            for (int b = 0; b < Bq; b++) {
                float4 v4 = *(const float4*)&s_h[b * 64 + i4];
                acc[b] = fmaf(v4.x, w0, acc[b]);
                acc[b] = fmaf(v4.y, w1, acc[b]);
                acc[b] = fmaf(v4.z, w2, acc[b]);
                acc[b] = fmaf(v4.w, w3, acc[b]);
            }
        }
#pragma unroll
        for (int b = 0; b < Bq; b++) atomicAdd(&g_attn[b * Dq + j], acc[b]);
    }
    grid_bar();

    // ============ Stage C ============
    // C1: redundant per-block xmid -> h2 (smem) + router
    {
        float ss[Bq];
#pragma unroll
        for (int b = 0; b < Bq; b++) ss[b] = 0.f;
#pragma unroll
        for (int it = 0; it < 4; it++) {
            int d = tid + it * 256;
#pragma unroll
            for (int b = 0; b < Bq; b++) {
                float xm = hidden[(size_t)b * Sq * Dq + d] + g_attn[b * Dq + d];
                ss[b] += xm * xm;
            }
        }
        breduce<Bq>(ss, s_red, s_out);
        if (tid < Bq) s_rs[tid] = rsqrtf(s_out[tid] * (1.f / Dq) + EPSq);
        __syncthreads();
        float l[16];
#pragma unroll
        for (int k = 0; k < 16; k++) l[k] = 0.f;
#pragma unroll
        for (int it = 0; it < 4; it++) {
            int d = tid + it * 256;
            float r0 = rw[d * 2 + 0], r1 = rw[d * 2 + 1], w2d = ln2w[d];
#pragma unroll
            for (int b = 0; b < Bq; b++) {
                float xm = hidden[(size_t)b * Sq * Dq + d] + g_attn[b * Dq + d];
                float h2 = xm * s_rs[b] * w2d;
                s_h[b * Dq + d] = h2;
                l[b]     = fmaf(h2, r0, l[b]);
                l[8 + b] = fmaf(h2, r1, l[8 + b]);
            }
        }
        breduce<16>(l, s_red, s_out);
        if (tid < Bq) {
            float l0 = s_out[tid], l1 = s_out[8 + tid];
            s_sel[tid] = (l1 > l0) ? 1 : 0;
            s_tw[tid]  = 1.f / (1.f + expf(-fabsf(l0 - l1)));
        }
        __syncthreads();
    }

    // C2: gate/up matvec (224 tasks: e x 8 i-chunks x 14 f-chunks)
    if (blk < 224) {
        int e = blk / 112, r = blk % 112, ic = r / 14, fc = r % 14;
        bool used = false;
#pragma unroll
        for (int b = 0; b < Bq; b++) used |= (s_sel[b] == e);
        if (used) {
            int f = fc * 256 + tid, ib = ic * 128;
            const float* gp = gw + (size_t)e * Dq * Fq + f;
            const float* up = uw + (size_t)e * Dq * Fq + f;
            float ag[Bq], au[Bq];
#pragma unroll
            for (int b = 0; b < Bq; b++) { ag[b] = 0.f; au[b] = 0.f; }
            for (int i4 = 0; i4 < 128; i4 += 4) {
                int i = ib + i4;
                float4 h4[Bq];
#pragma unroll
                for (int b = 0; b < Bq; b++) h4[b] = *(const float4*)&s_h[b * Dq + i];
#pragma unroll
                for (int u2 = 0; u2 < 4; u2++) {
                    float wg = gp[(size_t)(i + u2) * Fq];
                    float wu = up[(size_t)(i + u2) * Fq];
#pragma unroll
                    for (int b = 0; b < Bq; b++) {
                        float hv = ((const float*)&h4[b])[u2];
                        ag[b] = fmaf(hv, wg, ag[b]);
                        au[b] = fmaf(hv, wu, au[b]);
                    }
                }
            }
#pragma unroll
            for (int b = 0; b < Bq; b++) {
                atomicAdd(&g_accg[((size_t)e * Bq + b) * Fq + f], ag[b]);
                atomicAdd(&g_accu[((size_t)e * Bq + b) * Fq + f], au[b]);
            }
        }
    }
    grid_bar();

    // ============ Stage D: silu/mask + down matvec ============
    // 224 tasks: e x 28 f-chunks(128) x 4 d-chunks(256)
    if (blk < 224) {
        int e = blk / 112, r = blk % 112, fc = r / 4, dc = r % 4;
        bool used = false;
#pragma unroll
        for (int b = 0; b < Bq; b++) used |= (s_sel[b] == e);
        if (used) {
            // build t [b][fl] into smem
            for (int idx = tid; idx < Bq * 128; idx += NT) {
                int b = idx >> 7, fl = idx & 127;
                float tv = 0.f;
                if (s_sel[b] == e) {
                    int f = fc * 128 + fl;
                    float gg = g_accg[((size_t)e * Bq + b) * Fq + f];
                    float uu = g_accu[((size_t)e * Bq + b) * Fq + f];
                    tv = s_tw[b] * gg * (1.f / (1.f + expf(-gg))) * uu;
                }
                s_h[idx] = tv;
            }
            __syncthreads();
            int d = dc * 256 + tid;
            const float* dp = dw + ((size_t)e * Fq + fc * 128) * Dq + d;
            float acc[Bq];
#pragma unroll
            for (int b = 0; b < Bq; b++) acc[b] = 0.f;
            for (int f4 = 0; f4 < 128; f4 += 4) {
                float w0 = dp[(size_t)(f4 + 0) * Dq];
                float w1 = dp[(size_t)(f4 + 1) * Dq];
                float w2 = dp[(size_t)(f4 + 2) * Dq];
                float w3 = dp[(size_t)(f4 + 3) * Dq];
#pragma unroll
                for (int b = 0; b < Bq; b++) {
                    float4 t4 = *(const float4*)&s_h[b * 128 + f4];
                    acc[b] = fmaf(t4.x, w0, acc[b]);
                    acc[b] = fmaf(t4.y, w1, acc[b]);
                    acc[b] = fmaf(t4.z, w2, acc[b]);
                    acc[b] = fmaf(t4.w, w3, acc[b]);
                }
            }
#pragma unroll
            for (int b = 0; b < Bq; b++) atomicAdd(&g_y[b * Dq + d], acc[b]);
        }
    }
    grid_bar();

    // ============ Stage E: final rmsnorm + score head (8 blocks) ============
    if (blk < Bq) {
        int b = blk;
        float xr[4];
        float ssv[1]; ssv[0] = 0.f;
#pragma unroll
        for (int it = 0; it < 4; it++) {
            int d = tid + it * 256;
            xr[it] = hidden[(size_t)b * Sq * Dq + d] + g_attn[b * Dq + d] + g_y[b * Dq + d];
            ssv[0] += xr[it] * xr[it];
        }
        breduce<1>(ssv, s_red, s_out);
        if (tid == 0) s_rs[0] = rsqrtf(s_out[0] * (1.f / Dq) + EPSq);
        __syncthreads();
        float rs = s_rs[0];
        float p[2]; p[0] = 0.f; p[1] = 0.f;
#pragma unroll
        for (int it = 0; it < 4; it++) {
            int d = tid + it * 256;
            float xn = xr[it] * rs * flnw[d];
            p[0] = fmaf(xn, sw[d * 2 + 0], p[0]);
            p[1] = fmaf(xn, sw[d * 2 + 1], p[1]);
        }
        breduce<2>(p, s_red, s_out);
        if (tid == 0) {
            out[b * 2 + 0] = s_out[0];
            out[b * 2 + 1] = s_out[1];
        }
    }
}

// ---------------- launch ----------------
extern "C" void kernel_launch(void* const* d_in, const int* in_sizes, int n_in,
                              void* d_out, int out_size) {
    (void)in_sizes; (void)n_in; (void)out_size;
    const float* hidden = (const float*)d_in[0];
    const float* ln1w   = (const float*)d_in[1];
    // d_in[2]=q_w, d_in[3]=k_w: provably unused (causal token-0 softmax == 1)
    const float* vw     = (const float*)d_in[4];
    const float* ow     = (const float*)d_in[5];
    const float* ln2w   = (const float*)d_in[6];
    const float* rw     = (const float*)d_in[7];
    const float* gw     = (const float*)d_in[8];
    const float* uw     = (const float*)d_in[9];
    const float* dw     = (const float*)d_in[10];
    const float* flnw   = (const float*)d_in[11];
    const float* sw     = (const float*)d_in[12];
    float* out = (float*)d_out;

    fused_all<<<NB, NT>>>(hidden, ln1w, vw, ow, ln2w, rw, gw, uw, dw, flnw, sw, out);
}

// round 3
// speedup vs baseline: 5.0904x; 1.2081x over previous
#include <cuda_runtime.h>
#include <math.h>

#define Bq 8
#define Sq 1024
#define Dq 1024
#define Fq 3584
#define Eq 2
#define NB 256
#define NT 256
#define EPSq 1e-6f

typedef unsigned long long ull;

// ---------------- device scratch (no allocation) ----------------
__device__ ull   g_pvu[64 * 4 * Dq];        // v0 partials [ic*4+p][j] (b-pairs)
__device__ float g_attn[Bq * Dq];           // attn output (atomic)
__device__ float g_accg[Eq * Bq * Fq];      // gate acc (atomic)
__device__ float g_accu[Eq * Bq * Fq];      // up acc (atomic)
__device__ float g_y[Bq * Dq];              // moe output (atomic)
__device__ unsigned g_barc = 0;
__device__ unsigned g_barg = 0;

// ---------------- f32x2 helpers ----------------
__device__ __forceinline__ ull pack2(float lo, float hi) {
    ull r;
    asm("mov.b64 %0, {%1, %2};" : "=l"(r) : "r"(__float_as_uint(lo)), "r"(__float_as_uint(hi)));
    return r;
}
__device__ __forceinline__ void unpack2(ull v, float& lo, float& hi) {
    unsigned a, b;
    asm("mov.b64 {%0, %1}, %2;" : "=r"(a), "=r"(b) : "l"(v));
    lo = __uint_as_float(a); hi = __uint_as_float(b);
}
#define FMA2(d, a, b) asm("fma.rn.f32x2 %0, %1, %2, %0;" : "+l"(d) : "l"(a), "l"(b))
#define ADD2(d, a)    asm("add.rn.f32x2 %0, %0, %1;"     : "+l"(d) : "l"(a))

// ---------------- software grid barrier ----------------
__device__ __forceinline__ void grid_bar() {
    __syncthreads();
    if (threadIdx.x == 0) {
        __threadfence();
        unsigned old = *(volatile unsigned*)&g_barg;
        if (atomicAdd(&g_barc, 1u) == (unsigned)gridDim.x - 1u) {
            g_barc = 0;
            __threadfence();
            atomicExch(&g_barg, old + 1u);
        } else {
            while (*(volatile unsigned*)&g_barg == old) __nanosleep(64);
        }
        __threadfence();
    }
    __syncthreads();
}

// ---------------- multi-value block reduction (8 warps) ----------
template <int NV>
__device__ __forceinline__ void breduce(const float* v, float* s_red, float* s_out) {
    int lane = threadIdx.x & 31, w = threadIdx.x >> 5;
#pragma unroll
    for (int k = 0; k < NV; k++) {
        float x = v[k];
#pragma unroll
        for (int o = 16; o; o >>= 1) x += __shfl_xor_sync(0xffffffffu, x, o);
        if (lane == 0) s_red[k * 8 + w] = x;
    }
    __syncthreads();
    if (threadIdx.x < NV) {
        float s = 0.f;
#pragma unroll
        for (int j = 0; j < 8; j++) s += s_red[threadIdx.x * 8 + j];
        s_out[threadIdx.x] = s;
    }
    __syncthreads();
}

__global__ void __launch_bounds__(NT, 2) fused_all(
    const float* __restrict__ hidden, const float* __restrict__ ln1w,
    const float* __restrict__ vw, const float* __restrict__ ow,
    const float* __restrict__ ln2w, const float* __restrict__ rw,
    const float* __restrict__ gw, const float* __restrict__ uw,
    const float* __restrict__ dw, const float* __restrict__ flnw,
    const float* __restrict__ sw, float* __restrict__ out)
{
    __shared__ float s_ht[Dq * Bq];   // 32KB: activation transposed [d][b]; reused for t in D
    __shared__ float s_v[16 * Bq];    // gathered v0 chunk [i][b]
    __shared__ float s_red[16 * 8];
    __shared__ float s_out[16];
    __shared__ float s_rs[Bq];
    __shared__ int   s_sel[Bq];
    __shared__ float s_tw[Bq];

    const int tid = threadIdx.x;
    const int blk = blockIdx.x;
    ull* s_htu = (ull*)s_ht;
    ull* s_vu  = (ull*)s_v;

    // ============ Stage A ============
    // A0: zero atomic accumulators
    for (int idx = blk * NT + tid; idx < Eq * Bq * Fq; idx += NB * NT) {
        g_accg[idx] = 0.f; g_accu[idx] = 0.f;
    }
    for (int idx = blk * NT + tid; idx < Bq * Dq; idx += NB * NT) {
        g_attn[idx] = 0.f; g_y[idx] = 0.f;
    }

    // A1: redundant per-block h1 = rmsnorm(x0)*ln1_w  -> s_ht[d][b]
    {
        float ss[Bq];
#pragma unroll
        for (int b = 0; b < Bq; b++) ss[b] = 0.f;
#pragma unroll
        for (int it = 0; it < 4; it++) {
            int d = tid + it * 256;
#pragma unroll
            for (int b = 0; b < Bq; b++) {
                float v = hidden[(size_t)b * Sq * Dq + d];
                ss[b] += v * v;
            }
        }
        breduce<Bq>(ss, s_red, s_out);
        if (tid < Bq) s_rs[tid] = rsqrtf(s_out[tid] * (1.f / Dq) + EPSq);
        __syncthreads();
#pragma unroll
        for (int it = 0; it < 4; it++) {
            int d = tid + it * 256;
            float lw = ln1w[d];
#pragma unroll
            for (int b = 0; b < Bq; b++)
                s_ht[d * Bq + b] = hidden[(size_t)b * Sq * Dq + d] * s_rs[b] * lw;
        }
        __syncthreads();
    }

    // A2: v0 partials. 256 tasks: 64 i-chunks(16) x 4 j-chunks(256)
    {
        int ic = blk >> 2, jc = blk & 3;
        int j = jc * 256 + tid, ib = ic * 16;
        float w[16];
#pragma unroll
        for (int u = 0; u < 16; u++) w[u] = vw[(size_t)(ib + u) * Dq + j];
        ull acc[4] = {0, 0, 0, 0};
#pragma unroll
        for (int u = 0; u < 16; u++) {
            ull w2 = pack2(w[u], w[u]);
#pragma unroll
            for (int p = 0; p < 4; p++) FMA2(acc[p], s_htu[(ib + u) * 4 + p], w2);
        }
#pragma unroll
        for (int p = 0; p < 4; p++) g_pvu[(size_t)(ic * 4 + p) * Dq + j] = acc[p];
    }
    grid_bar();

    // ============ Stage B: attn = v0 @ o_w ============
    {
        int ic = blk >> 2, jc = blk & 3;
        int ib = ic * 16;
        // gather full v0 for rows [ib, ib+16)
        if (tid < 64) {
            int i = tid >> 2, p = tid & 3;
            ull s = 0;
#pragma unroll 8
            for (int c = 0; c < 64; c++) {
                ull v = g_pvu[(size_t)(c * 4 + p) * Dq + ib + i];
                ADD2(s, v);
            }
            s_vu[i * 4 + p] = s;
        }
        __syncthreads();
        int j = jc * 256 + tid;
        float w[16];
#pragma unroll
        for (int u = 0; u < 16; u++) w[u] = ow[(size_t)(ib + u) * Dq + j];
        ull acc[4] = {0, 0, 0, 0};
#pragma unroll
        for (int u = 0; u < 16; u++) {
            ull w2 = pack2(w[u], w[u]);
#pragma unroll
            for (int p = 0; p < 4; p++) FMA2(acc[p], s_vu[u * 4 + p], w2);
        }
#pragma unroll
        for (int p = 0; p < 4; p++) {
            float lo, hi; unpack2(acc[p], lo, hi);
            atomicAdd(&g_attn[(2 * p) * Dq + j], lo);
            atomicAdd(&g_attn[(2 * p + 1) * Dq + j], hi);
        }
    }
    grid_bar();

    // ============ Stage C1: xmid -> h2 (s_ht transposed) + router ============
    {
        __syncthreads();
        float ss[Bq];
#pragma unroll
        for (int b = 0; b < Bq; b++) ss[b] = 0.f;
#pragma unroll
        for (int it = 0; it < 4; it++) {
            int d = tid + it * 256;
#pragma unroll
            for (int b = 0; b < Bq; b++) {
                float xm = hidden[(size_t)b * Sq * Dq + d] + g_attn[b * Dq + d];
                ss[b] += xm * xm;
            }
        }
        breduce<Bq>(ss, s_red, s_out);
        if (tid < Bq) s_rs[tid] = rsqrtf(s_out[tid] * (1.f / Dq) + EPSq);
        __syncthreads();
        float l[16];
#pragma unroll
        for (int k = 0; k < 16; k++) l[k] = 0.f;
#pragma unroll
        for (int it = 0; it < 4; it++) {
            int d = tid + it * 256;
            float r0 = rw[d * 2 + 0], r1 = rw[d * 2 + 1], w2d = ln2w[d];
#pragma unroll
            for (int b = 0; b < Bq; b++) {
                float xm = hidden[(size_t)b * Sq * Dq + d] + g_attn[b * Dq + d];
                float h2 = xm * s_rs[b] * w2d;
                s_ht[d * Bq + b] = h2;
                l[b]     = fmaf(h2, r0, l[b]);
                l[8 + b] = fmaf(h2, r1, l[8 + b]);
            }
        }
        breduce<16>(l, s_red, s_out);
        if (tid < Bq) {
            float l0 = s_out[tid], l1 = s_out[8 + tid];
            s_sel[tid] = (l1 > l0) ? 1 : 0;
            s_tw[tid]  = 1.f / (1.f + expf(-fabsf(l0 - l1)));
        }
        __syncthreads();
    }

    // ============ Stage C2: gate/up. 256 tasks: e x 8 ic(128) x 16 fc(224) ====
    {
        int e = blk >> 7, r = blk & 127, ic = r >> 4, fc = r & 15;
        bool used = false;
#pragma unroll
        for (int b = 0; b < Bq; b++) used |= (s_sel[b] == e);
        if (used && tid < 224) {
            int f = fc * 224 + tid, ib = ic * 128;
            const float* gp = gw + (size_t)e * Dq * Fq + f;
            const float* up = uw + (size_t)e * Dq * Fq + f;
            ull ag[4] = {0, 0, 0, 0}, au[4] = {0, 0, 0, 0};
            for (int i8 = 0; i8 < 128; i8 += 8) {
                int i = ib + i8;
                float wg[8], wu[8];
#pragma unroll
                for (int u = 0; u < 8; u++) wg[u] = gp[(size_t)(i + u) * Fq];
#pragma unroll
                for (int u = 0; u < 8; u++) wu[u] = up[(size_t)(i + u) * Fq];
#pragma unroll
                for (int u = 0; u < 8; u++) {
                    ull wg2 = pack2(wg[u], wg[u]);
                    ull wu2 = pack2(wu[u], wu[u]);
#pragma unroll
                    for (int p = 0; p < 4; p++) {
                        ull h2 = s_htu[(i + u) * 4 + p];
                        FMA2(ag[p], h2, wg2);
                        FMA2(au[p], h2, wu2);
                    }
                }
            }
#pragma unroll
            for (int p = 0; p < 4; p++) {
                float lo, hi;
                unpack2(ag[p], lo, hi);
                atomicAdd(&g_accg[((size_t)e * Bq + 2 * p) * Fq + f], lo);
                atomicAdd(&g_accg[((size_t)e * Bq + 2 * p + 1) * Fq + f], hi);
                unpack2(au[p], lo, hi);
                atomicAdd(&g_accu[((size_t)e * Bq + 2 * p) * Fq + f], lo);
                atomicAdd(&g_accu[((size_t)e * Bq + 2 * p + 1) * Fq + f], hi);
            }
        }
    }
    grid_bar();

    // ============ Stage D: silu/mask + down. 256 tasks: e x 32 fc(112) x 4 dc(256)
    {
        int e = blk >> 7, r = blk & 127, fc = r >> 2, dc = r & 3;
        bool used = false;
#pragma unroll
        for (int b = 0; b < Bq; b++) used |= (s_sel[b] == e);
        if (used) {
            int f0 = fc * 112;
            // build t [fl][b] into s_ht front (f-major, b-pairs)
            for (int idx = tid; idx < Bq * 112; idx += NT) {
                int b = idx / 112, fl = idx % 112;
                float tv = 0.f;
                if (s_sel[b] == e) {
                    int f = f0 + fl;
                    float gg = g_accg[((size_t)e * Bq + b) * Fq + f];
                    float uu = g_accu[((size_t)e * Bq + b) * Fq + f];
                    tv = s_tw[b] * gg * (1.f / (1.f + expf(-gg))) * uu;
                }
                s_ht[fl * Bq + b] = tv;
            }
            __syncthreads();
            int d = dc * 256 + tid;
            const float* dp = dw + ((size_t)e * Fq + f0) * Dq + d;
            ull acc[4] = {0, 0, 0, 0};
            for (int f8 = 0; f8 < 112; f8 += 8) {
                float w[8];
#pragma unroll
                for (int u = 0; u < 8; u++) w[u] = dp[(size_t)(f8 + u) * Dq];
#pragma unroll
                for (int u = 0; u < 8; u++) {
                    ull w2 = pack2(w[u], w[u]);
#pragma unroll
                    for (int p = 0; p < 4; p++) FMA2(acc[p], s_htu[(f8 + u) * 4 + p], w2);
                }
            }
#pragma unroll
            for (int p = 0; p < 4; p++) {
                float lo, hi; unpack2(acc[p], lo, hi);
                atomicAdd(&g_y[(2 * p) * Dq + d], lo);
                atomicAdd(&g_y[(2 * p + 1) * Dq + d], hi);
            }
        }
    }
    grid_bar();

    // ============ Stage E: final rmsnorm + score head (8 blocks) ============
    if (blk < Bq) {
        int b = blk;
        float xr[4];
        float ssv[1]; ssv[0] = 0.f;
#pragma unroll
        for (int it = 0; it < 4; it++) {
            int d = tid + it * 256;
            xr[it] = hidden[(size_t)b * Sq * Dq + d] + g_attn[b * Dq + d] + g_y[b * Dq + d];
            ssv[0] += xr[it] * xr[it];
        }
        breduce<1>(ssv, s_red, s_out);
        if (tid == 0) s_rs[0] = rsqrtf(s_out[0] * (1.f / Dq) + EPSq);
        __syncthreads();
        float rs = s_rs[0];
        float p[2]; p[0] = 0.f; p[1] = 0.f;
#pragma unroll
        for (int it = 0; it < 4; it++) {
            int d = tid + it * 256;
            float xn = xr[it] * rs * flnw[d];
            p[0] = fmaf(xn, sw[d * 2 + 0], p[0]);
            p[1] = fmaf(xn, sw[d * 2 + 1], p[1]);
        }
        breduce<2>(p, s_red, s_out);
        if (tid == 0) {
            out[b * 2 + 0] = s_out[0];
            out[b * 2 + 1] = s_out[1];
        }
    }
}

// ---------------- launch ----------------
extern "C" void kernel_launch(void* const* d_in, const int* in_sizes, int n_in,
                              void* d_out, int out_size) {
    (void)in_sizes; (void)n_in; (void)out_size;
    const float* hidden = (const float*)d_in[0];
    const float* ln1w   = (const float*)d_in[1];
    // d_in[2]=q_w, d_in[3]=k_w: provably unused (causal token-0 softmax == 1)
    const float* vw     = (const float*)d_in[4];
    const float* ow     = (const float*)d_in[5];
    const float* ln2w   = (const float*)d_in[6];
    const float* rw     = (const float*)d_in[7];
    const float* gw     = (const float*)d_in[8];
    const float* uw     = (const float*)d_in[9];
    const float* dw     = (const float*)d_in[10];
    const float* flnw   = (const float*)d_in[11];
    const float* sw     = (const float*)d_in[12];
    float* out = (float*)d_out;

    fused_all<<<NB, NT>>>(hidden, ln1w, vw, ow, ln2w, rw, gw, uw, dw, flnw, sw, out);
}